// round 14
// baseline (speedup 1.0000x reference)
#include <cuda_runtime.h>
#include <cuda_bf16.h>
#include <math.h>
#include <stdint.h>

#define N_ROWS 16384
#define D_DIM  1024
#define G_DIM  4096

#define DECAY    0.97f
#define ONE_M_D  (1.0f - 0.97f)
#define INV_TEMP (1.0f / 0.7f)
#define EPS_     1e-6f
#define NORM_EPS 1e-12f

// ---------------- scratch (device globals; no runtime allocation) -------------
__device__ __nv_bfloat16 g_Qb[(size_t)N_ROWS * D_DIM];
__device__ __nv_bfloat16 g_Pb[(size_t)G_DIM * D_DIM];
__device__ __nv_bfloat16 g_Wt[(size_t)G_DIM * N_ROWS];   // 128 MB
__device__ __nv_bfloat16 g_Xt[(size_t)D_DIM * N_ROWS];   // 32 MB
__device__ float g_h[G_DIM];
__device__ float g_ws[G_DIM];

// ============================ PTX helpers =====================================
__device__ __forceinline__ uint32_t smem_u32(const void* p) {
    uint32_t a;
    asm("{ .reg .u64 t; cvta.to.shared.u64 t, %1; cvt.u32.u64 %0, t; }" : "=r"(a) : "l"(p));
    return a;
}
__device__ __forceinline__ void cp16(uint32_t s, const void* g) {
    asm volatile("cp.async.cg.shared.global [%0], [%1], 16;" :: "r"(s), "l"(g));
}
__device__ __forceinline__ void cp_commit() {
    asm volatile("cp.async.commit_group;" ::: "memory");
}
template <int Nw>
__device__ __forceinline__ void cp_wait() {
    asm volatile("cp.async.wait_group %0;" :: "n"(Nw) : "memory");
}
__device__ __forceinline__ void ldsm4(uint32_t& r0, uint32_t& r1, uint32_t& r2, uint32_t& r3,
                                      uint32_t addr) {
    asm volatile("ldmatrix.sync.aligned.m8n8.x4.shared.b16 {%0,%1,%2,%3}, [%4];"
                 : "=r"(r0), "=r"(r1), "=r"(r2), "=r"(r3) : "r"(addr));
}
__device__ __forceinline__ void mma16816(float* c, const uint32_t* a, const uint32_t* b) {
    asm volatile(
        "mma.sync.aligned.m16n8k16.row.col.f32.bf16.bf16.f32 "
        "{%0,%1,%2,%3}, {%4,%5,%6,%7}, {%8,%9}, {%0,%1,%2,%3};"
        : "+f"(c[0]), "+f"(c[1]), "+f"(c[2]), "+f"(c[3])
        : "r"(a[0]), "r"(a[1]), "r"(a[2]), "r"(a[3]), "r"(b[0]), "r"(b[1]));
}

// ====================== block reductions (256 threads) ========================
__device__ __forceinline__ float warpSum(float v) {
#pragma unroll
    for (int o = 16; o; o >>= 1) v += __shfl_xor_sync(0xffffffffu, v, o);
    return v;
}
__device__ __forceinline__ float warpMax(float v) {
#pragma unroll
    for (int o = 16; o; o >>= 1) v = fmaxf(v, __shfl_xor_sync(0xffffffffu, v, o));
    return v;
}
__device__ __forceinline__ float blockSum(float v, float* sh) {
    __syncthreads();
    v = warpSum(v);
    if ((threadIdx.x & 31) == 0) sh[threadIdx.x >> 5] = v;
    __syncthreads();
    float r = sh[0];
#pragma unroll
    for (int i = 1; i < 8; i++) r += sh[i];
    return r;
}
__device__ __forceinline__ float blockMax(float v, float* sh) {
    __syncthreads();
    v = warpMax(v);
    if ((threadIdx.x & 31) == 0) sh[threadIdx.x >> 5] = v;
    __syncthreads();
    float r = sh[0];
#pragma unroll
    for (int i = 1; i < 8; i++) r = fmaxf(r, sh[i]);
    return r;
}

// ============================== small kernels =================================
__global__ void prep_kernel(const float* __restrict__ usage) {
    int g = blockIdx.x * 256 + threadIdx.x;
    if (g < G_DIM) {
        g_h[g] = logf(fmaxf(usage[g], EPS_));
        g_ws[g] = 0.0f;
    }
}

__global__ __launch_bounds__(256) void rownorm_kernel(const float* __restrict__ in,
                                                      __nv_bfloat16* __restrict__ out) {
    __shared__ float red[8];
    size_t row = blockIdx.x;
    float4 v = ((const float4*)(in + row * D_DIM))[threadIdx.x];
    float ss = v.x * v.x + v.y * v.y + v.z * v.z + v.w * v.w;
    ss = blockSum(ss, red);
    float sc = 1.0f / fmaxf(sqrtf(ss), NORM_EPS);
    unsigned short b[4];
    b[0] = __bfloat16_as_ushort(__float2bfloat16(v.x * sc));
    b[1] = __bfloat16_as_ushort(__float2bfloat16(v.y * sc));
    b[2] = __bfloat16_as_ushort(__float2bfloat16(v.z * sc));
    b[3] = __bfloat16_as_ushort(__float2bfloat16(v.w * sc));
    uint2 u = {((uint32_t)b[1] << 16) | b[0], ((uint32_t)b[3] << 16) | b[2]};
    *(uint2*)(out + row * D_DIM + threadIdx.x * 4) = u;
}

__global__ __launch_bounds__(256) void transpose_bf16_kernel(const float* __restrict__ src,
                                                             __nv_bfloat16* __restrict__ dst,
                                                             int R, int C) {
    __shared__ float tile[32][33];
    int c0 = blockIdx.x * 32, r0 = blockIdx.y * 32;
    int tx = threadIdx.x & 31, ty = threadIdx.x >> 5;
#pragma unroll
    for (int i = 0; i < 32; i += 8)
        tile[ty + i][tx] = src[(size_t)(r0 + ty + i) * C + c0 + tx];
    __syncthreads();
#pragma unroll
    for (int i = 0; i < 32; i += 8)
        dst[(size_t)(c0 + ty + i) * R + r0 + tx] = __float2bfloat16(tile[tx][ty + i]);
}

// fused: W [N,G] fp32 -> Wt [G,N] bf16, plus column sums into g_ws (measured win)
__global__ __launch_bounds__(256) void colsum_transpose_kernel(const float* __restrict__ W,
                                                               __nv_bfloat16* __restrict__ Wt) {
    __shared__ float tile[32][33];
    __shared__ float scol[32];
    int c0 = blockIdx.x * 32, r0 = blockIdx.y * 32;
    int tx = threadIdx.x & 31, ty = threadIdx.x >> 5;
    if (threadIdx.x < 32) scol[threadIdx.x] = 0.0f;
    __syncthreads();
    float psum = 0.0f;
#pragma unroll
    for (int i = 0; i < 32; i += 8) {
        float v = W[(size_t)(r0 + ty + i) * G_DIM + c0 + tx];
        tile[ty + i][tx] = v;
        psum += v;
    }
    atomicAdd(&scol[tx], psum);
    __syncthreads();
#pragma unroll
    for (int i = 0; i < 32; i += 8)
        Wt[(size_t)(c0 + ty + i) * N_ROWS + r0 + tx] = __float2bfloat16(tile[tx][ty + i]);
    if (threadIdx.x < 32) atomicAdd(&g_ws[c0 + threadIdx.x], scol[threadIdx.x]);
}

__global__ __launch_bounds__(256) void softmax_kernel(float* __restrict__ W) {
    __shared__ float red[8];
    size_t row = blockIdx.x;
    float* r = W + row * (size_t)G_DIM;
    float loc[16];
    float m = -1e30f;
#pragma unroll
    for (int i = 0; i < 16; i++) {
        int g = threadIdx.x + i * 256;
        float s = (r[g] - g_h[g]) * INV_TEMP;
        loc[i] = s;
        m = fmaxf(m, s);
    }
    m = blockMax(m, red);
    float sum = 0.0f;
#pragma unroll
    for (int i = 0; i < 16; i++) {
        loc[i] = expf(loc[i] - m);
        sum += loc[i];
    }
    sum = blockSum(sum, red);
    float inv = 1.0f / sum;
#pragma unroll
    for (int i = 0; i < 16; i++) r[threadIdx.x + i * 256] = loc[i] * inv;
}

__global__ __launch_bounds__(256) void finalize_kernel(const float* __restrict__ patterns,
                                                       const float* __restrict__ usage,
                                                       float* __restrict__ p_out,
                                                       float* __restrict__ u_out) {
    __shared__ float red[8];
    int g = blockIdx.x;
    float ws = g_ws[g];
    bool valid = ws > 0.0f;
    float inv = 1.0f / (ws + EPS_);

    float4 pv = ((const float4*)(patterns + (size_t)g * D_DIM))[threadIdx.x];
    float4* out4 = (float4*)(p_out + (size_t)g * D_DIM);
    float4 uv = out4[threadIdx.x];
    float4 b;
    b.x = pv.x * DECAY + ONE_M_D * (uv.x * inv);
    b.y = pv.y * DECAY + ONE_M_D * (uv.y * inv);
    b.z = pv.z * DECAY + ONE_M_D * (uv.z * inv);
    b.w = pv.w * DECAY + ONE_M_D * (uv.w * inv);
    float ss = b.x * b.x + b.y * b.y + b.z * b.z + b.w * b.w;
    ss = blockSum(ss, red);
    float sc = 1.0f / fmaxf(sqrtf(ss), NORM_EPS);
    float4 o;
    if (valid) { o.x = b.x * sc; o.y = b.y * sc; o.z = b.z * sc; o.w = b.w * sc; }
    else       { o = pv; }
    out4[threadIdx.x] = o;

    if (threadIdx.x == 0) {
        float un = usage[g] * DECAY;
        if (valid) un += ONE_M_D * ws;
        u_out[g] = un;
    }
}

// ================= bf16 NT GEMM via mma.sync (HMMA tensor pipe) ===============
// C[m,n] = sum_k A[m,k] * B[n,k]; A [M,K], B [Nc,K] bf16 K-major, C [M,Nc] fp32.
// 128x128x64 CTA tile, 4-stage cp.async (32KB/stage, 128KB), 8 warps (2m x 4n).
// 1 CTA/SM with FRAGMENT DOUBLE-BUFFERING: ldsm for kk+1 overlaps MMAs of kk,
// cross-stage prefetch at kk=3 (wait<1> -> sync -> ldsm next stage kk0).
#define BMm 128
#define BNm 128
#define BKm 64
#define NSTG 4
#define STG_BYTES ((BMm + BNm) * 128)  // 32768
#define GTHREADS 256

__global__ __launch_bounds__(GTHREADS) void mma_gemm_nt(const __nv_bfloat16* __restrict__ A,
                                                        const __nv_bfloat16* __restrict__ B,
                                                        float* __restrict__ C,
                                                        int M, int Nc, int K) {
    extern __shared__ char sm[];
    uint32_t sbase = smem_u32(sm);
    int tid = threadIdx.x;
    int wid = tid >> 5, lane = tid & 31;
    int wm = wid & 1, wn = wid >> 1;  // 2m x 4n, warp tile 64x32
    int bm = blockIdx.y * BMm, bn = blockIdx.x * BNm;
    int niter = K / BKm;

    float acc[4][4][4];
#pragma unroll
    for (int i = 0; i < 4; i++)
#pragma unroll
        for (int j = 0; j < 4; j++)
#pragma unroll
            for (int q = 0; q < 4; q++) acc[i][j][q] = 0.0f;

    // loader: 256 rows x 128B = 2048 16B chunks, 256 threads -> 8 each
    auto load_stage = [&](int s, int ki) {
        uint32_t st = sbase + s * STG_BYTES;
        int k0 = ki * BKm;
#pragma unroll
        for (int i = 0; i < 8; i++) {
            int lin = tid + i * GTHREADS;
            int r = lin >> 3, ch = lin & 7;
            uint32_t sw = (uint32_t)r * 128 + (uint32_t)(ch ^ (r & 7)) * 16;
            const __nv_bfloat16* src =
                (r < BMm) ? A + (size_t)(bm + r) * K + k0 + ch * 8
                          : B + (size_t)(bn + r - BMm) * K + k0 + ch * 8;
            cp16(st + sw, src);
        }
    };

#pragma unroll
    for (int s = 0; s < NSTG - 1; s++) {
        load_stage(s, s);
        cp_commit();
    }

    int lr = lane & 15, lc = lane >> 4;

    // double-buffered fragments
    uint32_t afr[2][4][4];
    uint32_t bfr[2][4][2];

    // load A+B fragments for chunk ch (0..7) of stage base st into buffer buf
#define LOAD_FRAGS(buf, st, chv)                                                    \
    do {                                                                            \
        int _ch = (chv);                                                            \
        _Pragma("unroll")                                                           \
        for (int mt = 0; mt < 4; mt++) {                                            \
            int r = wm * 64 + mt * 16 + lr;                                         \
            uint32_t addr = (st) + (uint32_t)r * 128 + (uint32_t)(_ch ^ (r & 7)) * 16; \
            ldsm4(afr[buf][mt][0], afr[buf][mt][1], afr[buf][mt][2], afr[buf][mt][3], addr); \
        }                                                                           \
        _Pragma("unroll")                                                           \
        for (int bt = 0; bt < 2; bt++) {                                            \
            int r = BMm + wn * 32 + bt * 16 + lr;                                   \
            uint32_t addr = (st) + (uint32_t)r * 128 + (uint32_t)(_ch ^ (r & 7)) * 16; \
            uint32_t t0, t1, t2, t3;                                                \
            ldsm4(t0, t1, t2, t3, addr);                                            \
            bfr[buf][bt * 2 + 0][0] = t0; bfr[buf][bt * 2 + 0][1] = t2;             \
            bfr[buf][bt * 2 + 1][0] = t1; bfr[buf][bt * 2 + 1][1] = t3;             \
        }                                                                           \
    } while (0)

    cp_wait<NSTG - 2>();
    __syncthreads();
    int stage = 0;
    LOAD_FRAGS(0, sbase, lc);  // stage 0, kk=0 (ch = lc)

    for (int it = 0; it < niter; it++) {
        uint32_t st = sbase + stage * STG_BYTES;
        int nstage = (stage + 1 == NSTG) ? 0 : stage + 1;
#pragma unroll
        for (int kk = 0; kk < 4; kk++) {
            const int buf = kk & 1, nbuf = buf ^ 1;
            if (kk < 3) {
                LOAD_FRAGS(nbuf, st, (kk + 1) * 2 + lc);
            } else if (it + 1 < niter) {
                cp_wait<1>();          // guarantee stage it+1 resident
                __syncthreads();       // all warps done reading stage it-1
                LOAD_FRAGS(nbuf, sbase + (uint32_t)nstage * STG_BYTES, lc);
            }
#pragma unroll
            for (int mt = 0; mt < 4; mt++)
#pragma unroll
                for (int nt = 0; nt < 4; nt++)
                    mma16816(acc[mt][nt], afr[buf][mt], bfr[buf][nt]);
        }
        // refill the stage consumed in iteration it-1 (freed by the barrier above)
        if (it + NSTG - 1 < niter) {
            int ls = stage + (NSTG - 1);
            if (ls >= NSTG) ls -= NSTG;
            load_stage(ls, it + NSTG - 1);
        }
        cp_commit();
        stage = nstage;
    }

    // epilogue: direct fp32 stores
    int row0 = bm + wm * 64 + (lane >> 2);
    int col0 = bn + wn * 32 + (lane & 3) * 2;
#pragma unroll
    for (int mt = 0; mt < 4; mt++) {
#pragma unroll
        for (int nt = 0; nt < 4; nt++) {
            float2 v0 = {acc[mt][nt][0], acc[mt][nt][1]};
            float2 v1 = {acc[mt][nt][2], acc[mt][nt][3]};
            *(float2*)(C + (size_t)(row0 + mt * 16) * Nc + col0 + nt * 8) = v0;
            *(float2*)(C + (size_t)(row0 + mt * 16 + 8) * Nc + col0 + nt * 8) = v1;
        }
    }
#undef LOAD_FRAGS
}

// ================================ host ========================================
extern "C" void kernel_launch(void* const* d_in, const int* in_sizes, int n_in,
                              void* d_out, int out_size) {
    const float* pair     = (const float*)d_in[0];  // [N,D]
    const float* patterns = (const float*)d_in[1];  // [G,D]
    const float* usage    = (const float*)d_in[2];  // [G]

    float* out   = (float*)d_out;
    float* w_out = out;                            // [N,G]
    float* p_out = out + (size_t)N_ROWS * G_DIM;   // [G,D]
    float* u_out = p_out + (size_t)G_DIM * D_DIM;  // [G]

    __nv_bfloat16 *Qb, *Pb, *Wt, *Xt;
    cudaGetSymbolAddress((void**)&Qb, g_Qb);
    cudaGetSymbolAddress((void**)&Pb, g_Pb);
    cudaGetSymbolAddress((void**)&Wt, g_Wt);
    cudaGetSymbolAddress((void**)&Xt, g_Xt);

    static bool attr_done = false;
    if (!attr_done) {
        cudaFuncSetAttribute((const void*)mma_gemm_nt,
                             cudaFuncAttributeMaxDynamicSharedMemorySize, NSTG * STG_BYTES);
        attr_done = true;
    }

    prep_kernel<<<G_DIM / 256, 256>>>(usage);
    rownorm_kernel<<<N_ROWS, 256>>>(pair, Qb);
    rownorm_kernel<<<G_DIM, 256>>>(patterns, Pb);

    // logits = Qn @ Pn^T
    mma_gemm_nt<<<dim3(G_DIM / BNm, N_ROWS / BMm), GTHREADS, NSTG * STG_BYTES>>>(
        Qb, Pb, w_out, N_ROWS, G_DIM, D_DIM);

    softmax_kernel<<<N_ROWS, 256>>>(w_out);

    // fused colsum + W transpose; X transpose
    colsum_transpose_kernel<<<dim3(G_DIM / 32, N_ROWS / 32), 256>>>(w_out, Wt);
    transpose_bf16_kernel<<<dim3(D_DIM / 32, N_ROWS / 32), 256>>>(pair, Xt, N_ROWS, D_DIM);

    // updates = W^T @ X = Wt @ Xt^T (NT form)
    mma_gemm_nt<<<dim3(D_DIM / BNm, G_DIM / BMm), GTHREADS, NSTG * STG_BYTES>>>(
        Wt, Xt, p_out, G_DIM, D_DIM, N_ROWS);

    finalize_kernel<<<G_DIM, 256>>>(patterns, usage, p_out, u_out);
}

// round 15
// speedup vs baseline: 1.0781x; 1.0781x over previous
#include <cuda_runtime.h>
#include <cuda_bf16.h>
#include <math.h>
#include <stdint.h>

#define N_ROWS 16384
#define D_DIM  1024
#define G_DIM  4096

#define DECAY    0.97f
#define ONE_M_D  (1.0f - 0.97f)
#define INV_TEMP (1.0f / 0.7f)
#define EPS_     1e-6f
#define NORM_EPS 1e-12f

// ---------------- scratch (device globals; no runtime allocation) -------------
__device__ __nv_bfloat16 g_Qb[(size_t)N_ROWS * D_DIM];
__device__ __nv_bfloat16 g_Pb[(size_t)G_DIM * D_DIM];
__device__ __nv_bfloat16 g_Wt[(size_t)G_DIM * N_ROWS];   // 128 MB
__device__ __nv_bfloat16 g_Xt[(size_t)D_DIM * N_ROWS];   // 32 MB
__device__ float g_h[G_DIM];
__device__ float g_ws[G_DIM];

// ============================ PTX helpers =====================================
__device__ __forceinline__ uint32_t smem_u32(const void* p) {
    uint32_t a;
    asm("{ .reg .u64 t; cvta.to.shared.u64 t, %1; cvt.u32.u64 %0, t; }" : "=r"(a) : "l"(p));
    return a;
}
__device__ __forceinline__ void cp16(uint32_t s, const void* g) {
    asm volatile("cp.async.cg.shared.global [%0], [%1], 16;" :: "r"(s), "l"(g));
}
__device__ __forceinline__ void cp_commit() {
    asm volatile("cp.async.commit_group;" ::: "memory");
}
template <int Nw>
__device__ __forceinline__ void cp_wait() {
    asm volatile("cp.async.wait_group %0;" :: "n"(Nw) : "memory");
}
__device__ __forceinline__ void ldsm4(uint32_t& r0, uint32_t& r1, uint32_t& r2, uint32_t& r3,
                                      uint32_t addr) {
    asm volatile("ldmatrix.sync.aligned.m8n8.x4.shared.b16 {%0,%1,%2,%3}, [%4];"
                 : "=r"(r0), "=r"(r1), "=r"(r2), "=r"(r3) : "r"(addr));
}
__device__ __forceinline__ void mma16816(float* c, const uint32_t* a, const uint32_t* b) {
    asm volatile(
        "mma.sync.aligned.m16n8k16.row.col.f32.bf16.bf16.f32 "
        "{%0,%1,%2,%3}, {%4,%5,%6,%7}, {%8,%9}, {%0,%1,%2,%3};"
        : "+f"(c[0]), "+f"(c[1]), "+f"(c[2]), "+f"(c[3])
        : "r"(a[0]), "r"(a[1]), "r"(a[2]), "r"(a[3]), "r"(b[0]), "r"(b[1]));
}

// ====================== block reductions (256 threads) ========================
__device__ __forceinline__ float warpSum(float v) {
#pragma unroll
    for (int o = 16; o; o >>= 1) v += __shfl_xor_sync(0xffffffffu, v, o);
    return v;
}
__device__ __forceinline__ float warpMax(float v) {
#pragma unroll
    for (int o = 16; o; o >>= 1) v = fmaxf(v, __shfl_xor_sync(0xffffffffu, v, o));
    return v;
}
__device__ __forceinline__ float blockSum(float v, float* sh) {
    __syncthreads();
    v = warpSum(v);
    if ((threadIdx.x & 31) == 0) sh[threadIdx.x >> 5] = v;
    __syncthreads();
    float r = sh[0];
#pragma unroll
    for (int i = 1; i < 8; i++) r += sh[i];
    return r;
}
__device__ __forceinline__ float blockMax(float v, float* sh) {
    __syncthreads();
    v = warpMax(v);
    if ((threadIdx.x & 31) == 0) sh[threadIdx.x >> 5] = v;
    __syncthreads();
    float r = sh[0];
#pragma unroll
    for (int i = 1; i < 8; i++) r = fmaxf(r, sh[i]);
    return r;
}

// ============================== small kernels =================================
__global__ void prep_kernel(const float* __restrict__ usage) {
    int g = blockIdx.x * 256 + threadIdx.x;
    if (g < G_DIM) {
        g_h[g] = logf(fmaxf(usage[g], EPS_));
        g_ws[g] = 0.0f;
    }
}

__global__ __launch_bounds__(256) void rownorm_kernel(const float* __restrict__ in,
                                                      __nv_bfloat16* __restrict__ out) {
    __shared__ float red[8];
    size_t row = blockIdx.x;
    float4 v = ((const float4*)(in + row * D_DIM))[threadIdx.x];
    float ss = v.x * v.x + v.y * v.y + v.z * v.z + v.w * v.w;
    ss = blockSum(ss, red);
    float sc = 1.0f / fmaxf(sqrtf(ss), NORM_EPS);
    unsigned short b[4];
    b[0] = __bfloat16_as_ushort(__float2bfloat16(v.x * sc));
    b[1] = __bfloat16_as_ushort(__float2bfloat16(v.y * sc));
    b[2] = __bfloat16_as_ushort(__float2bfloat16(v.z * sc));
    b[3] = __bfloat16_as_ushort(__float2bfloat16(v.w * sc));
    uint2 u = {((uint32_t)b[1] << 16) | b[0], ((uint32_t)b[3] << 16) | b[2]};
    *(uint2*)(out + row * D_DIM + threadIdx.x * 4) = u;
}

// fp32 [R, C] -> bf16 transposed [C, R]; vectorized 8B writes
__global__ __launch_bounds__(256) void transpose_bf16_kernel(const float* __restrict__ src,
                                                             __nv_bfloat16* __restrict__ dst,
                                                             int R, int C) {
    __shared__ float tile[32][33];
    int c0 = blockIdx.x * 32, r0 = blockIdx.y * 32;
    int tx = threadIdx.x & 31, ty = threadIdx.x >> 5;
#pragma unroll
    for (int i = 0; i < 32; i += 8)
        tile[ty + i][tx] = src[(size_t)(r0 + ty + i) * C + c0 + tx];
    __syncthreads();
    int ox = threadIdx.x & 7, oy = threadIdx.x >> 3;  // oy 0..31, ox 0..7
    unsigned short b[4];
#pragma unroll
    for (int j = 0; j < 4; j++)
        b[j] = __bfloat16_as_ushort(__float2bfloat16(tile[ox * 4 + j][oy]));
    uint2 u = {((uint32_t)b[1] << 16) | b[0], ((uint32_t)b[3] << 16) | b[2]};
    *(uint2*)(dst + (size_t)(c0 + oy) * R + r0 + ox * 4) = u;
}

// fused: W [N,G] fp32 -> Wt [G,N] bf16, plus column sums into g_ws (measured win)
__global__ __launch_bounds__(256) void colsum_transpose_kernel(const float* __restrict__ W,
                                                               __nv_bfloat16* __restrict__ Wt) {
    __shared__ float tile[32][33];
    __shared__ float scol[32];
    int c0 = blockIdx.x * 32, r0 = blockIdx.y * 32;
    int tx = threadIdx.x & 31, ty = threadIdx.x >> 5;
    if (threadIdx.x < 32) scol[threadIdx.x] = 0.0f;
    __syncthreads();
    float psum = 0.0f;
#pragma unroll
    for (int i = 0; i < 32; i += 8) {
        float v = W[(size_t)(r0 + ty + i) * G_DIM + c0 + tx];
        tile[ty + i][tx] = v;
        psum += v;
    }
    atomicAdd(&scol[tx], psum);
    __syncthreads();
    int ox = threadIdx.x & 7, oy = threadIdx.x >> 3;
    unsigned short b[4];
#pragma unroll
    for (int j = 0; j < 4; j++)
        b[j] = __bfloat16_as_ushort(__float2bfloat16(tile[ox * 4 + j][oy]));
    uint2 u = {((uint32_t)b[1] << 16) | b[0], ((uint32_t)b[3] << 16) | b[2]};
    *(uint2*)(Wt + (size_t)(c0 + oy) * N_ROWS + r0 + ox * 4) = u;
    if (threadIdx.x < 32) atomicAdd(&g_ws[c0 + threadIdx.x], scol[threadIdx.x]);
}

// softmax over G=4096 per row, in place; float4-vectorized
__global__ __launch_bounds__(256) void softmax_kernel(float* __restrict__ W) {
    __shared__ float red[8];
    size_t row = blockIdx.x;
    float* r = W + row * (size_t)G_DIM;
    float4 loc[4];
    float m = -1e30f;
#pragma unroll
    for (int i = 0; i < 4; i++) {
        int g = threadIdx.x * 4 + i * 1024;
        float4 v = *(const float4*)(r + g);
        float4 h = *(const float4*)(g_h + g);
        v.x = (v.x - h.x) * INV_TEMP;
        v.y = (v.y - h.y) * INV_TEMP;
        v.z = (v.z - h.z) * INV_TEMP;
        v.w = (v.w - h.w) * INV_TEMP;
        loc[i] = v;
        m = fmaxf(m, fmaxf(fmaxf(v.x, v.y), fmaxf(v.z, v.w)));
    }
    m = blockMax(m, red);
    float sum = 0.0f;
#pragma unroll
    for (int i = 0; i < 4; i++) {
        loc[i].x = expf(loc[i].x - m);
        loc[i].y = expf(loc[i].y - m);
        loc[i].z = expf(loc[i].z - m);
        loc[i].w = expf(loc[i].w - m);
        sum += loc[i].x + loc[i].y + loc[i].z + loc[i].w;
    }
    sum = blockSum(sum, red);
    float inv = 1.0f / sum;
#pragma unroll
    for (int i = 0; i < 4; i++) {
        float4 o = {loc[i].x * inv, loc[i].y * inv, loc[i].z * inv, loc[i].w * inv};
        *(float4*)(r + threadIdx.x * 4 + i * 1024) = o;
    }
}

__global__ __launch_bounds__(256) void finalize_kernel(const float* __restrict__ patterns,
                                                       const float* __restrict__ usage,
                                                       float* __restrict__ p_out,
                                                       float* __restrict__ u_out) {
    __shared__ float red[8];
    int g = blockIdx.x;
    float ws = g_ws[g];
    bool valid = ws > 0.0f;
    float inv = 1.0f / (ws + EPS_);

    float4 pv = ((const float4*)(patterns + (size_t)g * D_DIM))[threadIdx.x];
    float4* out4 = (float4*)(p_out + (size_t)g * D_DIM);
    float4 uv = out4[threadIdx.x];
    float4 b;
    b.x = pv.x * DECAY + ONE_M_D * (uv.x * inv);
    b.y = pv.y * DECAY + ONE_M_D * (uv.y * inv);
    b.z = pv.z * DECAY + ONE_M_D * (uv.z * inv);
    b.w = pv.w * DECAY + ONE_M_D * (uv.w * inv);
    float ss = b.x * b.x + b.y * b.y + b.z * b.z + b.w * b.w;
    ss = blockSum(ss, red);
    float sc = 1.0f / fmaxf(sqrtf(ss), NORM_EPS);
    float4 o;
    if (valid) { o.x = b.x * sc; o.y = b.y * sc; o.z = b.z * sc; o.w = b.w * sc; }
    else       { o = pv; }
    out4[threadIdx.x] = o;

    if (threadIdx.x == 0) {
        float un = usage[g] * DECAY;
        if (valid) un += ONE_M_D * ws;
        u_out[g] = un;
    }
}

// ================= bf16 NT GEMM via mma.sync (HMMA tensor pipe) ===============
// R11-proven config: 128x128x64 CTA tile, 3-stage cp.async (32KB/stage, 96KB),
// 8 warps (2m x 4n), 64x32 warp tile, 2 CTAs/SM (regs ~127).
#define BMm 128
#define BNm 128
#define BKm 64
#define NSTG 3
#define STG_BYTES ((BMm + BNm) * 128)  // 32768
#define GTHREADS 256

__global__ __launch_bounds__(GTHREADS) void mma_gemm_nt(const __nv_bfloat16* __restrict__ A,
                                                        const __nv_bfloat16* __restrict__ B,
                                                        float* __restrict__ C,
                                                        int M, int Nc, int K) {
    extern __shared__ char sm[];
    uint32_t sbase = smem_u32(sm);
    int tid = threadIdx.x;
    int wid = tid >> 5, lane = tid & 31;
    int wm = wid & 1, wn = wid >> 1;  // 2m x 4n, warp tile 64x32
    int bm = blockIdx.y * BMm, bn = blockIdx.x * BNm;
    int niter = K / BKm;

    float acc[4][4][4];
#pragma unroll
    for (int i = 0; i < 4; i++)
#pragma unroll
        for (int j = 0; j < 4; j++)
#pragma unroll
            for (int q = 0; q < 4; q++) acc[i][j][q] = 0.0f;

    // loader: 256 rows x 128B = 2048 16B chunks, 256 threads -> 8 each
    auto load_stage = [&](int s, int ki) {
        uint32_t st = sbase + s * STG_BYTES;
        int k0 = ki * BKm;
#pragma unroll
        for (int i = 0; i < 8; i++) {
            int lin = tid + i * GTHREADS;
            int r = lin >> 3, ch = lin & 7;
            uint32_t sw = (uint32_t)r * 128 + (uint32_t)(ch ^ (r & 7)) * 16;
            const __nv_bfloat16* src =
                (r < BMm) ? A + (size_t)(bm + r) * K + k0 + ch * 8
                          : B + (size_t)(bn + r - BMm) * K + k0 + ch * 8;
            cp16(st + sw, src);
        }
    };

#pragma unroll
    for (int s = 0; s < NSTG - 1; s++) {
        load_stage(s, s);
        cp_commit();
    }

    int lr = lane & 15, lc = lane >> 4;  // ldmatrix addressing
    int stage = 0;
    for (int it = 0; it < niter; it++) {
        cp_wait<NSTG - 2>();
        __syncthreads();
        if (it + NSTG - 1 < niter) {
            int ws_ = stage + (NSTG - 1);
            if (ws_ >= NSTG) ws_ -= NSTG;
            load_stage(ws_, it + NSTG - 1);
        }
        cp_commit();

        uint32_t st = sbase + stage * STG_BYTES;
#pragma unroll
        for (int kk = 0; kk < 4; kk++) {
            int ch = kk * 2 + lc;
            uint32_t afr[4][4];
#pragma unroll
            for (int mt = 0; mt < 4; mt++) {
                int r = wm * 64 + mt * 16 + lr;
                uint32_t addr = st + (uint32_t)r * 128 + (uint32_t)(ch ^ (r & 7)) * 16;
                ldsm4(afr[mt][0], afr[mt][1], afr[mt][2], afr[mt][3], addr);
            }
            uint32_t bfr[4][2];
#pragma unroll
            for (int bt = 0; bt < 2; bt++) {
                int r = BMm + wn * 32 + bt * 16 + lr;
                uint32_t addr = st + (uint32_t)r * 128 + (uint32_t)(ch ^ (r & 7)) * 16;
                uint32_t t0, t1, t2, t3;
                ldsm4(t0, t1, t2, t3, addr);
                bfr[bt * 2 + 0][0] = t0; bfr[bt * 2 + 0][1] = t2;
                bfr[bt * 2 + 1][0] = t1; bfr[bt * 2 + 1][1] = t3;
            }
#pragma unroll
            for (int mt = 0; mt < 4; mt++)
#pragma unroll
                for (int nt = 0; nt < 4; nt++) mma16816(acc[mt][nt], afr[mt], bfr[nt]);
        }
        if (++stage == NSTG) stage = 0;
    }

    // epilogue: direct fp32 stores
    int row0 = bm + wm * 64 + (lane >> 2);
    int col0 = bn + wn * 32 + (lane & 3) * 2;
#pragma unroll
    for (int mt = 0; mt < 4; mt++) {
#pragma unroll
        for (int nt = 0; nt < 4; nt++) {
            float2 v0 = {acc[mt][nt][0], acc[mt][nt][1]};
            float2 v1 = {acc[mt][nt][2], acc[mt][nt][3]};
            *(float2*)(C + (size_t)(row0 + mt * 16) * Nc + col0 + nt * 8) = v0;
            *(float2*)(C + (size_t)(row0 + mt * 16 + 8) * Nc + col0 + nt * 8) = v1;
        }
    }
}

// ================================ host ========================================
extern "C" void kernel_launch(void* const* d_in, const int* in_sizes, int n_in,
                              void* d_out, int out_size) {
    const float* pair     = (const float*)d_in[0];  // [N,D]
    const float* patterns = (const float*)d_in[1];  // [G,D]
    const float* usage    = (const float*)d_in[2];  // [G]

    float* out   = (float*)d_out;
    float* w_out = out;                            // [N,G]
    float* p_out = out + (size_t)N_ROWS * G_DIM;   // [G,D]
    float* u_out = p_out + (size_t)G_DIM * D_DIM;  // [G]

    __nv_bfloat16 *Qb, *Pb, *Wt, *Xt;
    cudaGetSymbolAddress((void**)&Qb, g_Qb);
    cudaGetSymbolAddress((void**)&Pb, g_Pb);
    cudaGetSymbolAddress((void**)&Wt, g_Wt);
    cudaGetSymbolAddress((void**)&Xt, g_Xt);

    static bool attr_done = false;
    if (!attr_done) {
        cudaFuncSetAttribute((const void*)mma_gemm_nt,
                             cudaFuncAttributeMaxDynamicSharedMemorySize, NSTG * STG_BYTES);
        attr_done = true;
    }

    prep_kernel<<<G_DIM / 256, 256>>>(usage);
    rownorm_kernel<<<N_ROWS, 256>>>(pair, Qb);
    rownorm_kernel<<<G_DIM, 256>>>(patterns, Pb);

    // logits = Qn @ Pn^T
    mma_gemm_nt<<<dim3(G_DIM / BNm, N_ROWS / BMm), GTHREADS, NSTG * STG_BYTES>>>(
        Qb, Pb, w_out, N_ROWS, G_DIM, D_DIM);

    softmax_kernel<<<N_ROWS, 256>>>(w_out);

    // fused colsum + W transpose; X transpose
    colsum_transpose_kernel<<<dim3(G_DIM / 32, N_ROWS / 32), 256>>>(w_out, Wt);
    transpose_bf16_kernel<<<dim3(D_DIM / 32, N_ROWS / 32), 256>>>(pair, Xt, N_ROWS, D_DIM);

    // updates = W^T @ X = Wt @ Xt^T (NT form)
    mma_gemm_nt<<<dim3(D_DIM / BNm, G_DIM / BMm), GTHREADS, NSTG * STG_BYTES>>>(
        Wt, Xt, p_out, G_DIM, D_DIM, N_ROWS);

    finalize_kernel<<<G_DIM, 256>>>(patterns, usage, p_out, u_out);
}